// round 2
// baseline (speedup 1.0000x reference)
#include <cuda_runtime.h>
#include <math.h>

#define BATCH 2
#define HEADS 16
#define SEQ   2048
#define DIM   64
#define BH    (BATCH*HEADS)

#define BM 128           // query rows per block
#define BN 64            // keys per tile
#define QTS 132          // padded stride for transposed [DIM][BM] tiles (16B aligned, conflict-light)
#define KTS 68           // padded stride for [.][DIM] tiles

// Scratch for RoPE'd Q and K (allocation-free rule -> __device__ globals)
__device__ __align__(16) float g_Qr[BH*SEQ*DIM];
__device__ __align__(16) float g_Kr[BH*SEQ*DIM];

// ---------------------------------------------------------------------------
// RoPE: out[2i] = e*cos - o*sin ; out[2i+1] = e*sin + o*cos, ang = s * 10000^(-2i/64)
// ---------------------------------------------------------------------------
__global__ void rope_kernel(const float* __restrict__ Q, const float* __restrict__ K) {
    int idx = blockIdx.x * blockDim.x + threadIdx.x;   // one (row, pair) per thread
    const int half = DIM / 2;                          // 32
    const int total = BH * SEQ * half;
    if (idx >= total) return;
    int i   = idx & (half - 1);
    int row = idx >> 5;                                // bh*SEQ + s
    int s   = row & (SEQ - 1);

    // matches jnp: exp(2i * (-ln(10000)/64))
    float div = expf((float)(2 * i) * (-9.210340371976184f / 64.0f));
    float ang = (float)s * div;
    float sv, cv;
    sincosf(ang, &sv, &cv);

    int base = row * DIM + 2 * i;
    float qe = Q[base], qo = Q[base + 1];
    g_Qr[base]     = qe * cv - qo * sv;
    g_Qr[base + 1] = qe * sv + qo * cv;
    float ke = K[base], ko = K[base + 1];
    g_Kr[base]     = ke * cv - ko * sv;
    g_Kr[base + 1] = ke * sv + ko * cv;
}

// ---------------------------------------------------------------------------
// Flash attention, causal, fp32. 256 threads = 16(tx: col/dim groups) x 16(ty: row groups).
// Each thread owns an 8-row x 4-col register tile in both GEMMs.
// Smem: Qt [DIM][QTS] transposed Q, Kt [DIM][KTS] transposed K,
//       Vs [BN][KTS], Pt [BN][QTS] transposed probabilities.
// ---------------------------------------------------------------------------
__global__ __launch_bounds__(256) void flash_kernel(const float* __restrict__ Vall,
                                                    float* __restrict__ Og) {
    extern __shared__ float sm[];
    float* Qt = sm;                      // DIM*QTS
    float* Kt = Qt + DIM * QTS;          // DIM*KTS
    float* Vs = Kt + DIM * KTS;          // BN*KTS
    float* Pt = Vs + BN  * KTS;          // BN*QTS

    const int bh    = blockIdx.y;
    const int qtile = (gridDim.x - 1) - blockIdx.x;   // heavy tiles launch first
    const int q0    = qtile * BM;

    const float* Qg = g_Qr + (size_t)bh * SEQ * DIM;
    const float* Kg = g_Kr + (size_t)bh * SEQ * DIM;
    const float* Vg = Vall + (size_t)bh * SEQ * DIM;

    const int tid = threadIdx.x;
    const int tx  = tid & 15;
    const int ty  = tid >> 4;
    const int m0  = ty * 8;     // this thread's 8 query rows (within tile)
    const int n0  = tx * 4;     // this thread's 4 cols (keys in GEMM1, dims in GEMM2)

    // ---- load Q tile, transposed into Qt[d][m] ----
    #pragma unroll
    for (int r = 0; r < 8; r++) {
        int c  = tid + 256 * r;          // 0..2047 float4 chunks
        int m  = c >> 4;
        int d4 = (c & 15) << 2;
        float4 v = *(const float4*)(Qg + (size_t)(q0 + m) * DIM + d4);
        Qt[(d4 + 0) * QTS + m] = v.x;
        Qt[(d4 + 1) * QTS + m] = v.y;
        Qt[(d4 + 2) * QTS + m] = v.z;
        Qt[(d4 + 3) * QTS + m] = v.w;
    }

    float o[8][4];
    float mrow[8], lrow[8];
    #pragma unroll
    for (int i = 0; i < 8; i++) {
        mrow[i] = -INFINITY; lrow[i] = 0.f;
        #pragma unroll
        for (int j = 0; j < 4; j++) o[i][j] = 0.f;
    }

    const int ntiles = q0 / BN + 2;      // causal: tiles with kv0 <= q0+BM-1
    for (int t = 0; t < ntiles; t++) {
        const int kv0 = t * BN;

        __syncthreads();   // previous iteration done with Kt/Vs/Pt

        // ---- load K (transposed) and V tiles ----
        #pragma unroll
        for (int r = 0; r < 4; r++) {
            int c  = tid + 256 * r;       // 0..1023 float4 chunks
            int n  = c >> 4;
            int d4 = (c & 15) << 2;
            float4 kv = *(const float4*)(Kg + (size_t)(kv0 + n) * DIM + d4);
            Kt[(d4 + 0) * KTS + n] = kv.x;
            Kt[(d4 + 1) * KTS + n] = kv.y;
            Kt[(d4 + 2) * KTS + n] = kv.z;
            Kt[(d4 + 3) * KTS + n] = kv.w;
            *(float4*)(Vs + n * KTS + d4) =
                *(const float4*)(Vg + (size_t)(kv0 + n) * DIM + d4);
        }
        __syncthreads();

        // ---- GEMM1: S = Q @ K^T ----
        float sacc[8][4];
        #pragma unroll
        for (int i = 0; i < 8; i++)
            #pragma unroll
            for (int j = 0; j < 4; j++) sacc[i][j] = 0.f;

        #pragma unroll 16
        for (int k = 0; k < DIM; k++) {
            const float4 qa = *(const float4*)(Qt + k * QTS + m0);
            const float4 qb = *(const float4*)(Qt + k * QTS + m0 + 4);
            const float4 kb = *(const float4*)(Kt + k * KTS + n0);
            const float qm[8] = {qa.x, qa.y, qa.z, qa.w, qb.x, qb.y, qb.z, qb.w};
            const float kn[4] = {kb.x, kb.y, kb.z, kb.w};
            #pragma unroll
            for (int mi = 0; mi < 8; mi++)
                #pragma unroll
                for (int ni = 0; ni < 4; ni++)
                    sacc[mi][ni] = fmaf(qm[mi], kn[ni], sacc[mi][ni]);
        }

        // ---- causal mask + online softmax ----
        const bool diag = (kv0 + BN - 1 > q0);
        #pragma unroll
        for (int mi = 0; mi < 8; mi++) {
            const int qr = q0 + m0 + mi;
            if (diag) {
                #pragma unroll
                for (int ni = 0; ni < 4; ni++)
                    if (kv0 + n0 + ni > qr) sacc[mi][ni] = -INFINITY;
            }
            float rmax = fmaxf(fmaxf(sacc[mi][0], sacc[mi][1]),
                               fmaxf(sacc[mi][2], sacc[mi][3]));
            #pragma unroll
            for (int off = 8; off >= 1; off >>= 1)
                rmax = fmaxf(rmax, __shfl_xor_sync(0xffffffffu, rmax, off));

            const float mnew  = fmaxf(mrow[mi], rmax);
            const float alpha = (mrow[mi] == -INFINITY) ? 0.f : __expf(mrow[mi] - mnew);

            float rs = 0.f;
            #pragma unroll
            for (int ni = 0; ni < 4; ni++) {
                float pv = __expf(sacc[mi][ni] - mnew);   // -inf -> 0
                sacc[mi][ni] = pv;                        // reuse regs as P
                rs += pv;
            }
            #pragma unroll
            for (int off = 8; off >= 1; off >>= 1)
                rs += __shfl_xor_sync(0xffffffffu, rs, off);

            lrow[mi] = lrow[mi] * alpha + rs;
            mrow[mi] = mnew;
            #pragma unroll
            for (int di = 0; di < 4; di++) o[mi][di] *= alpha;
        }

        // ---- write P transposed: Pt[n][m] ----
        #pragma unroll
        for (int ni = 0; ni < 4; ni++) {
            *(float4*)(Pt + (n0 + ni) * QTS + m0) =
                make_float4(sacc[0][ni], sacc[1][ni], sacc[2][ni], sacc[3][ni]);
            *(float4*)(Pt + (n0 + ni) * QTS + m0 + 4) =
                make_float4(sacc[4][ni], sacc[5][ni], sacc[6][ni], sacc[7][ni]);
        }
        __syncthreads();

        // ---- GEMM2: O += P @ V ----
        #pragma unroll 16
        for (int n = 0; n < BN; n++) {
            const float4 pa = *(const float4*)(Pt + n * QTS + m0);
            const float4 pb = *(const float4*)(Pt + n * QTS + m0 + 4);
            const float4 vv = *(const float4*)(Vs + n * KTS + n0);
            const float pm[8] = {pa.x, pa.y, pa.z, pa.w, pb.x, pb.y, pb.z, pb.w};
            const float vd[4] = {vv.x, vv.y, vv.z, vv.w};
            #pragma unroll
            for (int mi = 0; mi < 8; mi++)
                #pragma unroll
                for (int di = 0; di < 4; di++)
                    o[mi][di] = fmaf(pm[mi], vd[di], o[mi][di]);
        }
    }

    // ---- epilogue: normalize and store ----
    #pragma unroll
    for (int mi = 0; mi < 8; mi++) {
        const float inv = 1.f / lrow[mi];
        float4 out = make_float4(o[mi][0] * inv, o[mi][1] * inv,
                                 o[mi][2] * inv, o[mi][3] * inv);
        *(float4*)(Og + (size_t)(bh * SEQ + q0 + m0 + mi) * DIM + n0) = out;
    }
}

// ---------------------------------------------------------------------------
extern "C" void kernel_launch(void* const* d_in, const int* in_sizes, int n_in,
                              void* d_out, int out_size) {
    const float* Q = (const float*)d_in[0];
    const float* K = (const float*)d_in[1];
    const float* V = (const float*)d_in[2];
    float* O = (float*)d_out;

    const size_t smem = (size_t)(DIM * QTS + DIM * KTS + BN * KTS + BN * QTS) * sizeof(float); // 102400B
    cudaFuncSetAttribute(flash_kernel, cudaFuncAttributeMaxDynamicSharedMemorySize, (int)smem);

    const int total = BH * SEQ * (DIM / 2);
    rope_kernel<<<(total + 255) / 256, 256>>>(Q, K);

    dim3 grid(SEQ / BM, BH);
    flash_kernel<<<grid, 256, smem>>>(V, O);
}

// round 5
// speedup vs baseline: 1.6056x; 1.6056x over previous
#include <cuda_runtime.h>
#include <math.h>
#include <stdint.h>

#define BATCH 2
#define HEADS 16
#define SEQ   2048
#define DIM   64
#define BH    (BATCH*HEADS)
#define BM    128
#define BN    64

#define KP2   66            // K smem pitch in float2 (hi,lo interleaved)
#define VP    68            // V smem pitch in floats
#define SM_K_BYTES (64*KP2*8)            // 33792
#define SM_TOTAL   (SM_K_BYTES + 64*VP*4) // 33792+17408 = 51200

__device__ __align__(16) float g_Qr[BH*SEQ*DIM];
__device__ __align__(16) float g_Kr[BH*SEQ*DIM];

// tf32 round-to-nearest; returns the b32 bit pattern (valid fp32 with 10-bit mantissa)
__device__ __forceinline__ uint32_t tf32u(float x) {
    uint32_t r; asm("cvt.rna.tf32.f32 %0, %1;" : "=r"(r) : "f"(x)); return r;
}
__device__ __forceinline__ float tf32f(float x) {
    return __uint_as_float(tf32u(x));
}

// D += A(16x8 tf32) * B(8x8 tf32), fp32 accum
__device__ __forceinline__ void mma8(float* c, const uint32_t* a, uint32_t b0, uint32_t b1) {
    asm volatile("mma.sync.aligned.m16n8k8.row.col.f32.tf32.tf32.f32 "
        "{%0,%1,%2,%3}, {%4,%5,%6,%7}, {%8,%9}, {%0,%1,%2,%3};"
        : "+f"(c[0]), "+f"(c[1]), "+f"(c[2]), "+f"(c[3])
        : "r"(a[0]), "r"(a[1]), "r"(a[2]), "r"(a[3]), "r"(b0), "r"(b1));
}

// ---------------------------------------------------------------------------
// RoPE precompute (fp32)
// ---------------------------------------------------------------------------
__global__ void rope_kernel(const float* __restrict__ Q, const float* __restrict__ K) {
    int idx = blockIdx.x * blockDim.x + threadIdx.x;
    const int half = DIM / 2;
    if (idx >= BH * SEQ * half) return;
    int i   = idx & (half - 1);
    int row = idx >> 5;
    int s   = row & (SEQ - 1);
    float div = expf((float)(2 * i) * (-9.210340371976184f / 64.0f));
    float sv, cv; sincosf((float)s * div, &sv, &cv);
    int base = row * DIM + 2 * i;
    float qe = Q[base], qo = Q[base + 1];
    g_Qr[base]     = qe * cv - qo * sv;
    g_Qr[base + 1] = qe * sv + qo * cv;
    float ke = K[base], ko = K[base + 1];
    g_Kr[base]     = ke * cv - ko * sv;
    g_Kr[base + 1] = ke * sv + ko * cv;
}

// ---------------------------------------------------------------------------
// mma.sync tf32 flash attention. 8 warps; warp w owns q rows [q0+16w, q0+16w+16).
// Per-thread fragment rows: r0 = gid, r1 = gid+8 (gid = lane>>2, ctg = lane&3).
// ---------------------------------------------------------------------------
__global__ __launch_bounds__(256, 1) void flash_kernel(const float* __restrict__ Vall,
                                                       float* __restrict__ Og) {
    extern __shared__ __align__(16) char dsm[];
    float2* Ksm = (float2*)dsm;                     // [key][dim] {hi,lo}, pitch KP2
    float*  Vsm = (float*)(dsm + SM_K_BYTES);       // [key][dim], pitch VP

    const int tid  = threadIdx.x;
    const int w    = tid >> 5;
    const int lane = tid & 31;
    const int gid  = lane >> 2;
    const int ctg  = lane & 3;

    const int bh = blockIdx.y;
    const int q0 = ((int)(gridDim.x - 1) - (int)blockIdx.x) * BM;   // heavy tiles first
    const float* Qg = g_Qr + ((size_t)bh * SEQ + q0 + w * 16) * DIM;
    const float* Kg = g_Kr + (size_t)bh * SEQ * DIM;
    const float* Vg = Vall + (size_t)bh * SEQ * DIM;

    // ---- persistent Q A-fragments (tf32 hi/lo) ----
    uint32_t qh[8][4], ql[8][4];
    #pragma unroll
    for (int kc = 0; kc < 8; kc++) {
        const int c0 = 8 * kc + ctg;
        float f0 = Qg[gid * DIM + c0];            // a0: (gid,   ctg)
        float f1 = Qg[(gid + 8) * DIM + c0];      // a1: (gid+8, ctg)
        float f2 = Qg[gid * DIM + c0 + 4];        // a2: (gid,   ctg+4)
        float f3 = Qg[(gid + 8) * DIM + c0 + 4];  // a3: (gid+8, ctg+4)
        qh[kc][0] = tf32u(f0); ql[kc][0] = tf32u(f0 - __uint_as_float(qh[kc][0]));
        qh[kc][1] = tf32u(f1); ql[kc][1] = tf32u(f1 - __uint_as_float(qh[kc][1]));
        qh[kc][2] = tf32u(f2); ql[kc][2] = tf32u(f2 - __uint_as_float(qh[kc][2]));
        qh[kc][3] = tf32u(f3); ql[kc][3] = tf32u(f3 - __uint_as_float(qh[kc][3]));
    }

    float o[8][4];
    #pragma unroll
    for (int j = 0; j < 8; j++) { o[j][0] = o[j][1] = o[j][2] = o[j][3] = 0.f; }
    float m0 = -INFINITY, m1 = -INFINITY, l0 = 0.f, l1 = 0.f;
    const int r0g = q0 + w * 16 + gid;
    const int r1g = r0g + 8;

    const int ntiles = q0 / BN + 2;
    for (int t = 0; t < ntiles; t++) {
        const int kv0 = t * BN;

        __syncthreads();
        // ---- stage K (hi/lo) and V tiles ----
        #pragma unroll
        for (int it = 0; it < 4; it++) {
            int c = tid + 256 * it;          // 1024 float4 chunks over 64x64
            int row = c >> 4, d4 = (c & 15) << 2;
            float4 k4 = *(const float4*)(Kg + (size_t)(kv0 + row) * DIM + d4);
            float hx = tf32f(k4.x), hy = tf32f(k4.y), hz = tf32f(k4.z), hw = tf32f(k4.w);
            float4 p0 = make_float4(hx, tf32f(k4.x - hx), hy, tf32f(k4.y - hy));
            float4 p1 = make_float4(hz, tf32f(k4.z - hz), hw, tf32f(k4.w - hw));
            float* kb = (float*)(Ksm + row * KP2 + d4);
            *(float4*)(kb)     = p0;
            *(float4*)(kb + 4) = p1;
            *(float4*)(Vsm + row * VP + d4) =
                *(const float4*)(Vg + (size_t)(kv0 + row) * DIM + d4);
        }
        __syncthreads();

        // ---- GEMM1: S = Q @ K^T  (3x tf32) ----
        float sacc[8][4];
        #pragma unroll
        for (int j = 0; j < 8; j++) {
            sacc[j][0] = sacc[j][1] = sacc[j][2] = sacc[j][3] = 0.f;
            const float2* krow = Ksm + (8 * j + gid) * KP2;
            #pragma unroll
            for (int kc = 0; kc < 8; kc++) {
                float2 b0 = krow[8 * kc + ctg];        // K[8j+gid][8kc+ctg] {hi,lo}
                float2 b1 = krow[8 * kc + ctg + 4];
                uint32_t bh0 = __float_as_uint(b0.x), bl0 = __float_as_uint(b0.y);
                uint32_t bh1 = __float_as_uint(b1.x), bl1 = __float_as_uint(b1.y);
                mma8(sacc[j], qh[kc], bh0, bh1);
                mma8(sacc[j], ql[kc], bh0, bh1);
                mma8(sacc[j], qh[kc], bl0, bl1);
            }
        }

        // ---- causal mask + online softmax (C layout: cols 2ctg,2ctg+1) ----
        float mx0 = -INFINITY, mx1 = -INFINITY;
        #pragma unroll
        for (int j = 0; j < 8; j++) {
            const int c0 = kv0 + 8 * j + 2 * ctg, c1 = c0 + 1;
            if (c0 > r0g) sacc[j][0] = -INFINITY;
            if (c1 > r0g) sacc[j][1] = -INFINITY;
            if (c0 > r1g) sacc[j][2] = -INFINITY;
            if (c1 > r1g) sacc[j][3] = -INFINITY;
            mx0 = fmaxf(mx0, fmaxf(sacc[j][0], sacc[j][1]));
            mx1 = fmaxf(mx1, fmaxf(sacc[j][2], sacc[j][3]));
        }
        mx0 = fmaxf(mx0, __shfl_xor_sync(0xffffffffu, mx0, 1));
        mx0 = fmaxf(mx0, __shfl_xor_sync(0xffffffffu, mx0, 2));
        mx1 = fmaxf(mx1, __shfl_xor_sync(0xffffffffu, mx1, 1));
        mx1 = fmaxf(mx1, __shfl_xor_sync(0xffffffffu, mx1, 2));

        const float mn0 = fmaxf(m0, mx0), mn1 = fmaxf(m1, mx1);
        const float a0s = __expf(m0 - mn0), a1s = __expf(m1 - mn1);
        float s0 = 0.f, s1 = 0.f;
        #pragma unroll
        for (int j = 0; j < 8; j++) {
            float p0 = __expf(sacc[j][0] - mn0), p1 = __expf(sacc[j][1] - mn0);
            float p2 = __expf(sacc[j][2] - mn1), p3 = __expf(sacc[j][3] - mn1);
            sacc[j][0] = p0; sacc[j][1] = p1; sacc[j][2] = p2; sacc[j][3] = p3;
            s0 += p0 + p1; s1 += p2 + p3;
        }
        s0 += __shfl_xor_sync(0xffffffffu, s0, 1);
        s0 += __shfl_xor_sync(0xffffffffu, s0, 2);
        s1 += __shfl_xor_sync(0xffffffffu, s1, 1);
        s1 += __shfl_xor_sync(0xffffffffu, s1, 2);
        l0 = l0 * a0s + s0; m0 = mn0;
        l1 = l1 * a1s + s1; m1 = mn1;
        #pragma unroll
        for (int j = 0; j < 8; j++) {
            o[j][0] *= a0s; o[j][1] *= a0s; o[j][2] *= a1s; o[j][3] *= a1s;
        }

        // ---- C-fragment -> A-fragment (P), via quad shuffles ----
        uint32_t pa[8][4];
        const int bl  = lane & ~3;
        const int sA  = bl + (ctg >> 1);          // source of col ctg
        const int sB  = sA + 2;                   // source of col ctg+4
        const bool oddc = (ctg & 1);
        #pragma unroll
        for (int j = 0; j < 8; j++) {
            float x0 = __shfl_sync(0xffffffffu, sacc[j][0], sA);
            float x1 = __shfl_sync(0xffffffffu, sacc[j][1], sA);
            float y0 = __shfl_sync(0xffffffffu, sacc[j][0], sB);
            float y1 = __shfl_sync(0xffffffffu, sacc[j][1], sB);
            float z0 = __shfl_sync(0xffffffffu, sacc[j][2], sA);
            float z1 = __shfl_sync(0xffffffffu, sacc[j][3], sA);
            float u0 = __shfl_sync(0xffffffffu, sacc[j][2], sB);
            float u1 = __shfl_sync(0xffffffffu, sacc[j][3], sB);
            pa[j][0] = tf32u(oddc ? x1 : x0);  // (gid,   ctg)
            pa[j][1] = tf32u(oddc ? z1 : z0);  // (gid+8, ctg)
            pa[j][2] = tf32u(oddc ? y1 : y0);  // (gid,   ctg+4)
            pa[j][3] = tf32u(oddc ? u1 : u0);  // (gid+8, ctg+4)
        }

        // ---- GEMM2: O += P @ V ----
        #pragma unroll
        for (int jd = 0; jd < 8; jd++) {
            #pragma unroll
            for (int kc = 0; kc < 8; kc++) {
                uint32_t b0 = tf32u(Vsm[(8 * kc + ctg) * VP + 8 * jd + gid]);
                uint32_t b1 = tf32u(Vsm[(8 * kc + ctg + 4) * VP + 8 * jd + gid]);
                mma8(o[jd], pa[kc], b0, b1);
            }
        }
    }

    // ---- epilogue ----
    const float i0 = 1.f / l0, i1 = 1.f / l1;
    float* out0 = Og + ((size_t)bh * SEQ + r0g) * DIM;
    float* out1 = Og + ((size_t)bh * SEQ + r1g) * DIM;
    #pragma unroll
    for (int jd = 0; jd < 8; jd++) {
        const int c = 8 * jd + 2 * ctg;
        *(float2*)(out0 + c) = make_float2(o[jd][0] * i0, o[jd][1] * i0);
        *(float2*)(out1 + c) = make_float2(o[jd][2] * i1, o[jd][3] * i1);
    }
}

// ---------------------------------------------------------------------------
extern "C" void kernel_launch(void* const* d_in, const int* in_sizes, int n_in,
                              void* d_out, int out_size) {
    const float* Q = (const float*)d_in[0];
    const float* K = (const float*)d_in[1];
    const float* V = (const float*)d_in[2];
    float* O = (float*)d_out;

    cudaFuncSetAttribute(flash_kernel, cudaFuncAttributeMaxDynamicSharedMemorySize, SM_TOTAL);

    const int total = BH * SEQ * (DIM / 2);
    rope_kernel<<<(total + 255) / 256, 256>>>(Q, K);

    dim3 grid(SEQ / BM, BH);
    flash_kernel<<<grid, 256, SM_TOTAL>>>(V, O);
}

// round 6
// speedup vs baseline: 1.9619x; 1.2220x over previous
#include <cuda_runtime.h>
#include <math.h>
#include <stdint.h>

#define BATCH 2
#define HEADS 16
#define SEQ   2048
#define DIM   64
#define BH    (BATCH*HEADS)
#define BM    128
#define BN    64

// fragment-layout smem: K block (j,kc) = 32 lanes x float4 {hi_c, lo_c, hi_c4, lo_c4}
//                       V block (kc,jd) = 32 lanes x float2 {V[8kc+c][8jd+g], V[8kc+c+4][8jd+g]}
#define KFP 528                 // 512 + 16 pad (bank rotate for staging stores)
#define VFP 264                 // 256 + 8 pad
#define SM_KF 0
#define SM_VF (64*KFP)          // 33792
#define SM_TOTAL (SM_VF + 64*VFP)  // 50688

__device__ __align__(16) float g_Qr[BH*SEQ*DIM];
__device__ __align__(16) float g_Kr[BH*SEQ*DIM];

__device__ __forceinline__ uint32_t tf32u(float x) {
    uint32_t r; asm("cvt.rna.tf32.f32 %0, %1;" : "=r"(r) : "f"(x)); return r;
}
__device__ __forceinline__ float tf32f(float x) {
    return __uint_as_float(tf32u(x));
}

__device__ __forceinline__ void mma8(float* c, const uint32_t* a, uint32_t b0, uint32_t b1) {
    asm volatile("mma.sync.aligned.m16n8k8.row.col.f32.tf32.tf32.f32 "
        "{%0,%1,%2,%3}, {%4,%5,%6,%7}, {%8,%9}, {%0,%1,%2,%3};"
        : "+f"(c[0]), "+f"(c[1]), "+f"(c[2]), "+f"(c[3])
        : "r"(a[0]), "r"(a[1]), "r"(a[2]), "r"(a[3]), "r"(b0), "r"(b1));
}

// ---------------------------------------------------------------------------
__global__ void rope_kernel(const float* __restrict__ Q, const float* __restrict__ K) {
    int idx = blockIdx.x * blockDim.x + threadIdx.x;
    const int half = DIM / 2;
    if (idx >= BH * SEQ * half) return;
    int i   = idx & (half - 1);
    int row = idx >> 5;
    int s   = row & (SEQ - 1);
    float div = expf((float)(2 * i) * (-9.210340371976184f / 64.0f));
    float sv, cv; sincosf((float)s * div, &sv, &cv);
    int base = row * DIM + 2 * i;
    float qe = Q[base], qo = Q[base + 1];
    g_Qr[base]     = qe * cv - qo * sv;
    g_Qr[base + 1] = qe * sv + qo * cv;
    float ke = K[base], ko = K[base + 1];
    g_Kr[base]     = ke * cv - ko * sv;
    g_Kr[base + 1] = ke * sv + ko * cv;
}

// ---------------------------------------------------------------------------
__global__ __launch_bounds__(256, 1) void flash_kernel(const float* __restrict__ Vall,
                                                       float* __restrict__ Og) {
    extern __shared__ __align__(16) char dsm[];

    const int tid  = threadIdx.x;
    const int w    = tid >> 5;
    const int lane = tid & 31;
    const int gid  = lane >> 2;
    const int ctg  = lane & 3;

    const int bh = blockIdx.y;
    const int q0 = ((int)(gridDim.x - 1) - (int)blockIdx.x) * BM;   // heavy tiles first
    const float* Qg = g_Qr + ((size_t)bh * SEQ + q0 + w * 16) * DIM;
    const float* Kg = g_Kr + (size_t)bh * SEQ * DIM;
    const float* Vg = Vall + (size_t)bh * SEQ * DIM;

    // ---- persistent Q A-fragments (tf32 hi/lo): 64 regs ----
    uint32_t qh[8][4], ql[8][4];
    #pragma unroll
    for (int kc = 0; kc < 8; kc++) {
        const int c0 = 8 * kc + ctg;
        float f0 = Qg[gid * DIM + c0];
        float f1 = Qg[(gid + 8) * DIM + c0];
        float f2 = Qg[gid * DIM + c0 + 4];
        float f3 = Qg[(gid + 8) * DIM + c0 + 4];
        qh[kc][0] = tf32u(f0); ql[kc][0] = tf32u(f0 - __uint_as_float(qh[kc][0]));
        qh[kc][1] = tf32u(f1); ql[kc][1] = tf32u(f1 - __uint_as_float(qh[kc][1]));
        qh[kc][2] = tf32u(f2); ql[kc][2] = tf32u(f2 - __uint_as_float(qh[kc][2]));
        qh[kc][3] = tf32u(f3); ql[kc][3] = tf32u(f3 - __uint_as_float(qh[kc][3]));
    }

    float o[8][4];
    #pragma unroll
    for (int j = 0; j < 8; j++) { o[j][0] = o[j][1] = o[j][2] = o[j][3] = 0.f; }
    float m0 = -INFINITY, m1 = -INFINITY, l0 = 0.f, l1 = 0.f;
    const int r0g = q0 + w * 16 + gid;
    const int r1g = r0g + 8;

    const int ntiles = q0 / BN + 2;
    for (int t = 0; t < ntiles; t++) {
        const int kv0 = t * BN;

        // ---- phase A: global loads (regs only; overlaps prev tile's MMAs) ----
        float4 kreg[4], vreg[4];
        #pragma unroll
        for (int it = 0; it < 4; it++) {
            int c = tid + 256 * it;
            int row = c >> 4, d4 = (c & 15) << 2;
            kreg[it] = *(const float4*)(Kg + (size_t)(kv0 + row) * DIM + d4);
            vreg[it] = *(const float4*)(Vg + (size_t)(kv0 + row) * DIM + d4);
        }
        __syncthreads();   // prior tile finished reading smem

        // ---- phase B: convert + store into fragment layout ----
        #pragma unroll
        for (int it = 0; it < 4; it++) {
            int c = tid + 256 * it;
            int row = c >> 4, d4 = (c & 15) << 2;
            // K: block (j,kc), lane g*4+i, halves at byte offset 0/8
            {
                int j = row >> 3, g = row & 7, kc = d4 >> 3;
                int half8 = (d4 & 4) ? 8 : 0;
                char* kb = dsm + SM_KF + (j * 8 + kc) * KFP + half8 + g * 64;
                float f[4] = {kreg[it].x, kreg[it].y, kreg[it].z, kreg[it].w};
                #pragma unroll
                for (int i = 0; i < 4; i++) {
                    float h = tf32f(f[i]);
                    *(float2*)(kb + i * 16) = make_float2(h, tf32f(f[i] - h));
                }
            }
            // V: block (kc,jd), lane g*4+cc, slot 0/4; tf32-rounded once here
            {
                int kc = row >> 3, r = row & 7, cc = r & 3;
                int slot = (r < 4) ? 0 : 4;
                int jd = d4 >> 3, gb = d4 & 7;
                char* vb = dsm + SM_VF + (kc * 8 + jd) * VFP + cc * 8 + slot + gb * 32;
                float f[4] = {vreg[it].x, vreg[it].y, vreg[it].z, vreg[it].w};
                #pragma unroll
                for (int i = 0; i < 4; i++)
                    *(float*)(vb + i * 32) = tf32f(f[i]);
            }
        }
        __syncthreads();

        // ---- GEMM1: S = Q @ K^T (3x tf32), one LDS.128 per (kc,j) ----
        float sacc[8][4];
        #pragma unroll
        for (int j = 0; j < 8; j++)
            sacc[j][0] = sacc[j][1] = sacc[j][2] = sacc[j][3] = 0.f;
        #pragma unroll
        for (int kc = 0; kc < 8; kc++) {
            #pragma unroll
            for (int j = 0; j < 8; j++) {
                float4 fr = *(const float4*)(dsm + SM_KF + (j * 8 + kc) * KFP + lane * 16);
                uint32_t bh0 = __float_as_uint(fr.x), bl0 = __float_as_uint(fr.y);
                uint32_t bh1 = __float_as_uint(fr.z), bl1 = __float_as_uint(fr.w);
                mma8(sacc[j], qh[kc], bh0, bh1);
                mma8(sacc[j], ql[kc], bh0, bh1);
                mma8(sacc[j], qh[kc], bl0, bl1);
            }
        }

        // ---- causal mask + online softmax ----
        float mx0 = -INFINITY, mx1 = -INFINITY;
        #pragma unroll
        for (int j = 0; j < 8; j++) {
            const int c0 = kv0 + 8 * j + 2 * ctg, c1 = c0 + 1;
            if (c0 > r0g) sacc[j][0] = -INFINITY;
            if (c1 > r0g) sacc[j][1] = -INFINITY;
            if (c0 > r1g) sacc[j][2] = -INFINITY;
            if (c1 > r1g) sacc[j][3] = -INFINITY;
            mx0 = fmaxf(mx0, fmaxf(sacc[j][0], sacc[j][1]));
            mx1 = fmaxf(mx1, fmaxf(sacc[j][2], sacc[j][3]));
        }
        mx0 = fmaxf(mx0, __shfl_xor_sync(0xffffffffu, mx0, 1));
        mx0 = fmaxf(mx0, __shfl_xor_sync(0xffffffffu, mx0, 2));
        mx1 = fmaxf(mx1, __shfl_xor_sync(0xffffffffu, mx1, 1));
        mx1 = fmaxf(mx1, __shfl_xor_sync(0xffffffffu, mx1, 2));

        const float mn0 = fmaxf(m0, mx0), mn1 = fmaxf(m1, mx1);
        const float a0s = __expf(m0 - mn0), a1s = __expf(m1 - mn1);
        float s0 = 0.f, s1 = 0.f;
        #pragma unroll
        for (int j = 0; j < 8; j++) {
            float p0 = __expf(sacc[j][0] - mn0), p1 = __expf(sacc[j][1] - mn0);
            float p2 = __expf(sacc[j][2] - mn1), p3 = __expf(sacc[j][3] - mn1);
            sacc[j][0] = p0; sacc[j][1] = p1; sacc[j][2] = p2; sacc[j][3] = p3;
            s0 += p0 + p1; s1 += p2 + p3;
        }
        s0 += __shfl_xor_sync(0xffffffffu, s0, 1);
        s0 += __shfl_xor_sync(0xffffffffu, s0, 2);
        s1 += __shfl_xor_sync(0xffffffffu, s1, 1);
        s1 += __shfl_xor_sync(0xffffffffu, s1, 2);
        l0 = l0 * a0s + s0; m0 = mn0;
        l1 = l1 * a1s + s1; m1 = mn1;
        #pragma unroll
        for (int j = 0; j < 8; j++) {
            o[j][0] *= a0s; o[j][1] *= a0s; o[j][2] *= a1s; o[j][3] *= a1s;
        }

        // ---- C-fragment -> A-fragment (P) via quad shuffles ----
        uint32_t pa[8][4];
        const int bl  = lane & ~3;
        const int sA  = bl + (ctg >> 1);
        const int sB  = sA + 2;
        const bool oddc = (ctg & 1);
        #pragma unroll
        for (int j = 0; j < 8; j++) {
            float x0 = __shfl_sync(0xffffffffu, sacc[j][0], sA);
            float x1 = __shfl_sync(0xffffffffu, sacc[j][1], sA);
            float y0 = __shfl_sync(0xffffffffu, sacc[j][0], sB);
            float y1 = __shfl_sync(0xffffffffu, sacc[j][1], sB);
            float z0 = __shfl_sync(0xffffffffu, sacc[j][2], sA);
            float z1 = __shfl_sync(0xffffffffu, sacc[j][3], sA);
            float u0 = __shfl_sync(0xffffffffu, sacc[j][2], sB);
            float u1 = __shfl_sync(0xffffffffu, sacc[j][3], sB);
            pa[j][0] = tf32u(oddc ? x1 : x0);
            pa[j][1] = tf32u(oddc ? z1 : z0);
            pa[j][2] = tf32u(oddc ? y1 : y0);
            pa[j][3] = tf32u(oddc ? u1 : u0);
        }

        // ---- GEMM2: O += P @ V — one LDS.64 per (kc,jd), no cvts ----
        #pragma unroll
        for (int kc = 0; kc < 8; kc++) {
            #pragma unroll
            for (int jd = 0; jd < 8; jd++) {
                float2 b = *(const float2*)(dsm + SM_VF + (kc * 8 + jd) * VFP + lane * 8);
                mma8(o[jd], pa[kc], __float_as_uint(b.x), __float_as_uint(b.y));
            }
        }
    }

    // ---- epilogue ----
    const float i0 = 1.f / l0, i1 = 1.f / l1;
    float* out0 = Og + ((size_t)bh * SEQ + r0g) * DIM;
    float* out1 = Og + ((size_t)bh * SEQ + r1g) * DIM;
    #pragma unroll
    for (int jd = 0; jd < 8; jd++) {
        const int c = 8 * jd + 2 * ctg;
        *(float2*)(out0 + c) = make_float2(o[jd][0] * i0, o[jd][1] * i0);
        *(float2*)(out1 + c) = make_float2(o[jd][2] * i1, o[jd][3] * i1);
    }
}

// ---------------------------------------------------------------------------
extern "C" void kernel_launch(void* const* d_in, const int* in_sizes, int n_in,
                              void* d_out, int out_size) {
    const float* Q = (const float*)d_in[0];
    const float* K = (const float*)d_in[1];
    const float* V = (const float*)d_in[2];
    float* O = (float*)d_out;

    cudaFuncSetAttribute(flash_kernel, cudaFuncAttributeMaxDynamicSharedMemorySize, SM_TOTAL);

    const int total = BH * SEQ * (DIM / 2);
    rope_kernel<<<(total + 255) / 256, 256>>>(Q, K);

    dim3 grid(SEQ / BM, BH);
    flash_kernel<<<grid, 256, SM_TOTAL>>>(V, O);
}

// round 7
// speedup vs baseline: 2.1513x; 1.0965x over previous
#include <cuda_runtime.h>
#include <math.h>
#include <stdint.h>

#define BATCH 2
#define HEADS 16
#define SEQ   2048
#define DIM   64
#define BH    (BATCH*HEADS)
#define BM    128
#define BN    64

// fragment-layout smem: K block (j,kc) = 32 lanes x float4 {hi_c, lo_c, hi_c4, lo_c4}
//                       V block (kc,jd) = 32 lanes x float2
#define KFP 528                  // 512 + 16 pad
#define VFP 264                  // 256 + 8 pad
#define KF_BYTES (64*KFP)        // 33792
#define BUF_BYTES (KF_BYTES + 64*VFP)   // 50688 per buffer
#define SM_QLF (2*BUF_BYTES)     // Q-lo fragments: 8 warps x 8 kc x 512B = 32768
#define SM_TOTAL (SM_QLF + 8*8*512)     // 134144

__device__ __align__(16) float g_Qr[BH*SEQ*DIM];
__device__ __align__(16) float g_Kr[BH*SEQ*DIM];

__device__ __forceinline__ uint32_t tf32u(float x) {
    uint32_t r; asm("cvt.rna.tf32.f32 %0, %1;" : "=r"(r) : "f"(x)); return r;
}
__device__ __forceinline__ float tf32f(float x) {
    return __uint_as_float(tf32u(x));
}

__device__ __forceinline__ void mma8(float* c, const uint32_t* a, uint32_t b0, uint32_t b1) {
    asm volatile("mma.sync.aligned.m16n8k8.row.col.f32.tf32.tf32.f32 "
        "{%0,%1,%2,%3}, {%4,%5,%6,%7}, {%8,%9}, {%0,%1,%2,%3};"
        : "+f"(c[0]), "+f"(c[1]), "+f"(c[2]), "+f"(c[3])
        : "r"(a[0]), "r"(a[1]), "r"(a[2]), "r"(a[3]), "r"(b0), "r"(b1));
}

// ---------------------------------------------------------------------------
__global__ void rope_kernel(const float* __restrict__ Q, const float* __restrict__ K) {
    int idx = blockIdx.x * blockDim.x + threadIdx.x;
    const int half = DIM / 2;
    if (idx >= BH * SEQ * half) return;
    int i   = idx & (half - 1);
    int row = idx >> 5;
    int s   = row & (SEQ - 1);
    float div = expf((float)(2 * i) * (-9.210340371976184f / 64.0f));
    float sv, cv; sincosf((float)s * div, &sv, &cv);
    int base = row * DIM + 2 * i;
    float qe = Q[base], qo = Q[base + 1];
    g_Qr[base]     = qe * cv - qo * sv;
    g_Qr[base + 1] = qe * sv + qo * cv;
    float ke = K[base], ko = K[base + 1];
    g_Kr[base]     = ke * cv - ko * sv;
    g_Kr[base + 1] = ke * sv + ko * cv;
}

// ---------------------------------------------------------------------------
__device__ __forceinline__ void stage_ldg(const float* __restrict__ Kg,
                                          const float* __restrict__ Vg,
                                          int kv0, int tid,
                                          float4* kreg, float4* vreg) {
    #pragma unroll
    for (int it = 0; it < 4; it++) {
        int c = tid + 256 * it;
        int row = c >> 4, d4 = (c & 15) << 2;
        kreg[it] = *(const float4*)(Kg + (size_t)(kv0 + row) * DIM + d4);
        vreg[it] = *(const float4*)(Vg + (size_t)(kv0 + row) * DIM + d4);
    }
}

__device__ __forceinline__ void stage_sts(char* buf, int tid,
                                          const float4* kreg, const float4* vreg) {
    #pragma unroll
    for (int it = 0; it < 4; it++) {
        int c = tid + 256 * it;
        int row = c >> 4, d4 = (c & 15) << 2;
        // K: block (j,kc), lane g*4+i, halves at byte offset 0/8
        {
            int j = row >> 3, g = row & 7, kc = d4 >> 3;
            int half8 = (d4 & 4) ? 8 : 0;
            char* kb = buf + (j * 8 + kc) * KFP + half8 + g * 64;
            float f[4] = {kreg[it].x, kreg[it].y, kreg[it].z, kreg[it].w};
            #pragma unroll
            for (int i = 0; i < 4; i++) {
                float h = tf32f(f[i]);
                *(float2*)(kb + i * 16) = make_float2(h, tf32f(f[i] - h));
            }
        }
        // V: block (kc,jd), tf32-rounded once here
        {
            int kc = row >> 3, r = row & 7, cc = r & 3;
            int slot = (r < 4) ? 0 : 4;
            int jd = d4 >> 3, gb = d4 & 7;
            char* vb = buf + KF_BYTES + (kc * 8 + jd) * VFP + cc * 8 + slot + gb * 32;
            float f[4] = {vreg[it].x, vreg[it].y, vreg[it].z, vreg[it].w};
            #pragma unroll
            for (int i = 0; i < 4; i++)
                *(float*)(vb + i * 32) = tf32f(f[i]);
        }
    }
}

// ---------------------------------------------------------------------------
__global__ __launch_bounds__(256, 1) void flash_kernel(const float* __restrict__ Vall,
                                                       float* __restrict__ Og) {
    extern __shared__ __align__(16) char dsm[];

    const int tid  = threadIdx.x;
    const int w    = tid >> 5;
    const int lane = tid & 31;
    const int gid  = lane >> 2;
    const int ctg  = lane & 3;

    const int bh = blockIdx.y;
    const int q0 = ((int)(gridDim.x - 1) - (int)blockIdx.x) * BM;   // heavy tiles first
    const float* Qg = g_Qr + ((size_t)bh * SEQ + q0 + w * 16) * DIM;
    const float* Kg = g_Kr + (size_t)bh * SEQ * DIM;
    const float* Vg = Vall + (size_t)bh * SEQ * DIM;

    // ---- persistent Q-hi A-fragments (32 regs); Q-lo to per-warp smem frags ----
    char* qlw = dsm + SM_QLF + w * 4096;
    uint32_t qh[8][4];
    #pragma unroll
    for (int kc = 0; kc < 8; kc++) {
        const int c0 = 8 * kc + ctg;
        float f0 = Qg[gid * DIM + c0];
        float f1 = Qg[(gid + 8) * DIM + c0];
        float f2 = Qg[gid * DIM + c0 + 4];
        float f3 = Qg[(gid + 8) * DIM + c0 + 4];
        qh[kc][0] = tf32u(f0);
        qh[kc][1] = tf32u(f1);
        qh[kc][2] = tf32u(f2);
        qh[kc][3] = tf32u(f3);
        float4 qlv;
        qlv.x = tf32f(f0 - __uint_as_float(qh[kc][0]));
        qlv.y = tf32f(f1 - __uint_as_float(qh[kc][1]));
        qlv.z = tf32f(f2 - __uint_as_float(qh[kc][2]));
        qlv.w = tf32f(f3 - __uint_as_float(qh[kc][3]));
        *(float4*)(qlw + kc * 512 + lane * 16) = qlv;
    }

    float o[8][4];
    #pragma unroll
    for (int j = 0; j < 8; j++) { o[j][0] = o[j][1] = o[j][2] = o[j][3] = 0.f; }
    float m0 = -INFINITY, m1 = -INFINITY, l0 = 0.f, l1 = 0.f;
    const int r0g = q0 + w * 16 + gid;
    const int r1g = r0g + 8;

    const int ntiles = q0 / BN + 2;

    // ---- prologue: stage tile 0 into buf0 ----
    {
        float4 kreg[4], vreg[4];
        stage_ldg(Kg, Vg, 0, tid, kreg, vreg);
        stage_sts(dsm, tid, kreg, vreg);
    }
    __syncthreads();

    for (int t = 0; t < ntiles; t++) {
        const int kv0 = t * BN;
        char* bufR = dsm + (t & 1) * BUF_BYTES;
        char* bufW = dsm + ((t & 1) ^ 1) * BUF_BYTES;
        const bool have_next = (t + 1 < ntiles);

        // ---- early LDG for tile t+1 (latency hidden under this tile's math) ----
        float4 kreg[4], vreg[4];
        if (have_next) stage_ldg(Kg, Vg, kv0 + BN, tid, kreg, vreg);

        // ---- GEMM1: S = Q @ K^T (3x tf32) ----
        float sacc[8][4];
        #pragma unroll
        for (int j = 0; j < 8; j++)
            sacc[j][0] = sacc[j][1] = sacc[j][2] = sacc[j][3] = 0.f;
        #pragma unroll
        for (int kc = 0; kc < 8; kc++) {
            float4 qlf = *(const float4*)(qlw + kc * 512 + lane * 16);
            uint32_t ql[4] = {__float_as_uint(qlf.x), __float_as_uint(qlf.y),
                              __float_as_uint(qlf.z), __float_as_uint(qlf.w)};
            #pragma unroll
            for (int j = 0; j < 8; j++) {
                float4 fr = *(const float4*)(bufR + (j * 8 + kc) * KFP + lane * 16);
                uint32_t bh0 = __float_as_uint(fr.x), bl0 = __float_as_uint(fr.y);
                uint32_t bh1 = __float_as_uint(fr.z), bl1 = __float_as_uint(fr.w);
                mma8(sacc[j], qh[kc], bh0, bh1);
                mma8(sacc[j], ql, bh0, bh1);
                mma8(sacc[j], qh[kc], bl0, bl1);
            }
        }

        // ---- causal mask + online softmax ----
        float mx0 = -INFINITY, mx1 = -INFINITY;
        #pragma unroll
        for (int j = 0; j < 8; j++) {
            const int c0 = kv0 + 8 * j + 2 * ctg, c1 = c0 + 1;
            if (c0 > r0g) sacc[j][0] = -INFINITY;
            if (c1 > r0g) sacc[j][1] = -INFINITY;
            if (c0 > r1g) sacc[j][2] = -INFINITY;
            if (c1 > r1g) sacc[j][3] = -INFINITY;
            mx0 = fmaxf(mx0, fmaxf(sacc[j][0], sacc[j][1]));
            mx1 = fmaxf(mx1, fmaxf(sacc[j][2], sacc[j][3]));
        }
        mx0 = fmaxf(mx0, __shfl_xor_sync(0xffffffffu, mx0, 1));
        mx0 = fmaxf(mx0, __shfl_xor_sync(0xffffffffu, mx0, 2));
        mx1 = fmaxf(mx1, __shfl_xor_sync(0xffffffffu, mx1, 1));
        mx1 = fmaxf(mx1, __shfl_xor_sync(0xffffffffu, mx1, 2));

        const float mn0 = fmaxf(m0, mx0), mn1 = fmaxf(m1, mx1);
        const float a0s = __expf(m0 - mn0), a1s = __expf(m1 - mn1);
        float s0 = 0.f, s1 = 0.f;
        #pragma unroll
        for (int j = 0; j < 8; j++) {
            float p0 = __expf(sacc[j][0] - mn0), p1 = __expf(sacc[j][1] - mn0);
            float p2 = __expf(sacc[j][2] - mn1), p3 = __expf(sacc[j][3] - mn1);
            sacc[j][0] = p0; sacc[j][1] = p1; sacc[j][2] = p2; sacc[j][3] = p3;
            s0 += p0 + p1; s1 += p2 + p3;
        }
        s0 += __shfl_xor_sync(0xffffffffu, s0, 1);
        s0 += __shfl_xor_sync(0xffffffffu, s0, 2);
        s1 += __shfl_xor_sync(0xffffffffu, s1, 1);
        s1 += __shfl_xor_sync(0xffffffffu, s1, 2);
        l0 = l0 * a0s + s0; m0 = mn0;
        l1 = l1 * a1s + s1; m1 = mn1;
        #pragma unroll
        for (int j = 0; j < 8; j++) {
            o[j][0] *= a0s; o[j][1] *= a0s; o[j][2] *= a1s; o[j][3] *= a1s;
        }

        // ---- C-fragment -> A-fragment (P) via quad shuffles ----
        uint32_t pa[8][4];
        const int bl  = lane & ~3;
        const int sA  = bl + (ctg >> 1);
        const int sB  = sA + 2;
        const bool oddc = (ctg & 1);
        #pragma unroll
        for (int j = 0; j < 8; j++) {
            float x0 = __shfl_sync(0xffffffffu, sacc[j][0], sA);
            float x1 = __shfl_sync(0xffffffffu, sacc[j][1], sA);
            float y0 = __shfl_sync(0xffffffffu, sacc[j][0], sB);
            float y1 = __shfl_sync(0xffffffffu, sacc[j][1], sB);
            float z0 = __shfl_sync(0xffffffffu, sacc[j][2], sA);
            float z1 = __shfl_sync(0xffffffffu, sacc[j][3], sA);
            float u0 = __shfl_sync(0xffffffffu, sacc[j][2], sB);
            float u1 = __shfl_sync(0xffffffffu, sacc[j][3], sB);
            pa[j][0] = tf32u(oddc ? x1 : x0);
            pa[j][1] = tf32u(oddc ? z1 : z0);
            pa[j][2] = tf32u(oddc ? y1 : y0);
            pa[j][3] = tf32u(oddc ? u1 : u0);
        }

        // ---- GEMM2: O += P @ V ----
        #pragma unroll
        for (int kc = 0; kc < 8; kc++) {
            #pragma unroll
            for (int jd = 0; jd < 8; jd++) {
                float2 b = *(const float2*)(bufR + KF_BYTES + (kc * 8 + jd) * VFP + lane * 8);
                mma8(o[jd], pa[kc], __float_as_uint(b.x), __float_as_uint(b.y));
            }
        }

        // ---- store staged tile t+1 into the other buffer ----
        if (have_next) stage_sts(bufW, tid, kreg, vreg);
        __syncthreads();
    }

    // ---- epilogue ----
    const float i0 = 1.f / l0, i1 = 1.f / l1;
    float* out0 = Og + ((size_t)bh * SEQ + r0g) * DIM;
    float* out1 = Og + ((size_t)bh * SEQ + r1g) * DIM;
    #pragma unroll
    for (int jd = 0; jd < 8; jd++) {
        const int c = 8 * jd + 2 * ctg;
        *(float2*)(out0 + c) = make_float2(o[jd][0] * i0, o[jd][1] * i0);
        *(float2*)(out1 + c) = make_float2(o[jd][2] * i1, o[jd][3] * i1);
    }
}

// ---------------------------------------------------------------------------
extern "C" void kernel_launch(void* const* d_in, const int* in_sizes, int n_in,
                              void* d_out, int out_size) {
    const float* Q = (const float*)d_in[0];
    const float* K = (const float*)d_in[1];
    const float* V = (const float*)d_in[2];
    float* O = (float*)d_out;

    cudaFuncSetAttribute(flash_kernel, cudaFuncAttributeMaxDynamicSharedMemorySize, SM_TOTAL);

    const int total = BH * SEQ * (DIM / 2);
    rope_kernel<<<(total + 255) / 256, 256>>>(Q, K);

    dim3 grid(SEQ / BM, BH);
    flash_kernel<<<grid, 256, SM_TOTAL>>>(V, O);
}

// round 9
// speedup vs baseline: 2.9407x; 1.3669x over previous
#include <cuda_runtime.h>
#include <cuda_bf16.h>
#include <math.h>
#include <stdint.h>

#define BATCH 2
#define HEADS 16
#define SEQ   2048
#define DIM   64
#define BH    (BATCH*HEADS)
#define BM    128
#define BN    64

// K fragment blocks (j,kc): kc in 0..3 (k16 chunks), 32 lanes x 16B {hi0,hi1,lo0,lo1}
// V fragment blocks (kc,jd): kc in 0..7 (k8 chunks),  32 lanes x 8B (tf32)
#define KFP 528                  // 512 + 16 pad
#define VFP 264                  // 256 + 8 pad
#define KF_BYTES (8*4*KFP)       // 16896
#define BUF_BYTES (KF_BYTES + 64*VFP)   // 33792
#define SM_TOTAL (2*BUF_BYTES)   // 67584

__device__ __align__(16) float g_Qr[BH*SEQ*DIM];
__device__ __align__(16) float g_Kr[BH*SEQ*DIM];

__device__ __forceinline__ uint32_t tf32u(float x) {
    uint32_t r; asm("cvt.rna.tf32.f32 %0, %1;" : "=r"(r) : "f"(x)); return r;
}
__device__ __forceinline__ float tf32f(float x) {
    return __uint_as_float(tf32u(x));
}

// split (f0,f1) into bf16 hi pair + bf16 residual pair, packed bf16x2 (low half = f0)
__device__ __forceinline__ void bsplit2(float f0, float f1, uint32_t& hi, uint32_t& lo) {
    __nv_bfloat16 h0 = __float2bfloat16_rn(f0);
    __nv_bfloat16 h1 = __float2bfloat16_rn(f1);
    float r0 = f0 - __bfloat162float(h0);
    float r1 = f1 - __bfloat162float(h1);
    __nv_bfloat162 H = {h0, h1};
    __nv_bfloat162 L = {__float2bfloat16_rn(r0), __float2bfloat16_rn(r1)};
    hi = *(uint32_t*)&H;
    lo = *(uint32_t*)&L;
}

// tf32 m16n8k8 (GEMM2)
__device__ __forceinline__ void mma8(float* c, const uint32_t* a, uint32_t b0, uint32_t b1) {
    asm volatile("mma.sync.aligned.m16n8k8.row.col.f32.tf32.tf32.f32 "
        "{%0,%1,%2,%3}, {%4,%5,%6,%7}, {%8,%9}, {%0,%1,%2,%3};"
        : "+f"(c[0]), "+f"(c[1]), "+f"(c[2]), "+f"(c[3])
        : "r"(a[0]), "r"(a[1]), "r"(a[2]), "r"(a[3]), "r"(b0), "r"(b1));
}
// bf16 m16n8k16 (GEMM1)
__device__ __forceinline__ void mma16(float* c, const uint32_t* a, uint32_t b0, uint32_t b1) {
    asm volatile("mma.sync.aligned.m16n8k16.row.col.f32.bf16.bf16.f32 "
        "{%0,%1,%2,%3}, {%4,%5,%6,%7}, {%8,%9}, {%0,%1,%2,%3};"
        : "+f"(c[0]), "+f"(c[1]), "+f"(c[2]), "+f"(c[3])
        : "r"(a[0]), "r"(a[1]), "r"(a[2]), "r"(a[3]), "r"(b0), "r"(b1));
}

// ---------------------------------------------------------------------------
__global__ void rope_kernel(const float* __restrict__ Q, const float* __restrict__ K) {
    int idx = blockIdx.x * blockDim.x + threadIdx.x;
    const int half = DIM / 2;
    if (idx >= BH * SEQ * half) return;
    int i   = idx & (half - 1);
    int row = idx >> 5;
    int s   = row & (SEQ - 1);
    float div = expf((float)(2 * i) * (-9.210340371976184f / 64.0f));
    float sv, cv; sincosf((float)s * div, &sv, &cv);
    int base = row * DIM + 2 * i;
    float qe = Q[base], qo = Q[base + 1];
    g_Qr[base]     = qe * cv - qo * sv;
    g_Qr[base + 1] = qe * sv + qo * cv;
    float ke = K[base], ko = K[base + 1];
    g_Kr[base]     = ke * cv - ko * sv;
    g_Kr[base + 1] = ke * sv + ko * cv;
}

// ---------------------------------------------------------------------------
__device__ __forceinline__ void stage_ldg(const float* __restrict__ Kg,
                                          const float* __restrict__ Vg,
                                          int kv0, int tid,
                                          float4* kreg, float4* vreg) {
    #pragma unroll
    for (int it = 0; it < 4; it++) {
        int c = tid + 256 * it;
        int row = c >> 4, d4 = (c & 15) << 2;
        kreg[it] = *(const float4*)(Kg + (size_t)(kv0 + row) * DIM + d4);
        vreg[it] = *(const float4*)(Vg + (size_t)(kv0 + row) * DIM + d4);
    }
}

__device__ __forceinline__ void stage_sts(char* buf, int tid,
                                          const float4* kreg, const float4* vreg) {
    #pragma unroll
    for (int it = 0; it < 4; it++) {
        int c = tid + 256 * it;
        int row = c >> 4, d4 = (c & 15) << 2;
        // K -> bf16 hi/lo fragment layout: block (j,kc), slot (g*4+c0), half at +4B
        {
            int j = row >> 3, g = row & 7;
            int kc = d4 >> 4;
            int pp = (d4 >> 1) & 7;          // even pair index in chunk
            int c0 = pp & 3, halfb = (pp >> 2) * 4;
            uint32_t hi0, lo0, hi1, lo1;
            bsplit2(kreg[it].x, kreg[it].y, hi0, lo0);
            bsplit2(kreg[it].z, kreg[it].w, hi1, lo1);
            char* kb = buf + (j * 4 + kc) * KFP + (g * 4 + c0) * 16 + halfb;
            *(uint32_t*)(kb)      = hi0;
            *(uint32_t*)(kb + 8)  = lo0;
            *(uint32_t*)(kb + 16) = hi1;
            *(uint32_t*)(kb + 24) = lo1;
        }
        // V: block (kc,jd), tf32-rounded once here
        {
            int kc = row >> 3, r = row & 7, cc = r & 3;
            int slot = (r < 4) ? 0 : 4;
            int jd = d4 >> 3, gb = d4 & 7;
            char* vb = buf + KF_BYTES + (kc * 8 + jd) * VFP + cc * 8 + slot + gb * 32;
            float f[4] = {vreg[it].x, vreg[it].y, vreg[it].z, vreg[it].w};
            #pragma unroll
            for (int i = 0; i < 4; i++)
                *(float*)(vb + i * 32) = tf32f(f[i]);
        }
    }
}

// ---------------------------------------------------------------------------
__global__ __launch_bounds__(256, 1) void flash_kernel(const float* __restrict__ Vall,
                                                       float* __restrict__ Og) {
    extern __shared__ __align__(16) char dsm[];

    const int tid  = threadIdx.x;
    const int w    = tid >> 5;
    const int lane = tid & 31;
    const int gid  = lane >> 2;
    const int ctg  = lane & 3;

    const int bh = blockIdx.y;
    const int q0 = ((int)(gridDim.x - 1) - (int)blockIdx.x) * BM;   // heavy tiles first
    const float* Qg = g_Qr + ((size_t)bh * SEQ + q0 + w * 16) * DIM;
    const float* Kg = g_Kr + (size_t)bh * SEQ * DIM;
    const float* Vg = Vall + (size_t)bh * SEQ * DIM;

    // ---- persistent Q A-fragments, bf16 hi/lo, m16n8k16 layout: 32 regs ----
    uint32_t qh[4][4], ql[4][4];
    #pragma unroll
    for (int kc = 0; kc < 4; kc++) {
        const int e0 = 16 * kc + 2 * ctg;
        bsplit2(Qg[gid * DIM + e0],           Qg[gid * DIM + e0 + 1],       qh[kc][0], ql[kc][0]);
        bsplit2(Qg[(gid + 8) * DIM + e0],     Qg[(gid + 8) * DIM + e0 + 1], qh[kc][1], ql[kc][1]);
        bsplit2(Qg[gid * DIM + e0 + 8],       Qg[gid * DIM + e0 + 9],       qh[kc][2], ql[kc][2]);
        bsplit2(Qg[(gid + 8) * DIM + e0 + 8], Qg[(gid + 8) * DIM + e0 + 9], qh[kc][3], ql[kc][3]);
    }

    float o[8][4];
    #pragma unroll
    for (int j = 0; j < 8; j++) { o[j][0] = o[j][1] = o[j][2] = o[j][3] = 0.f; }
    float m0 = -INFINITY, m1 = -INFINITY, l0 = 0.f, l1 = 0.f;
    const int r0g = q0 + w * 16 + gid;
    const int r1g = r0g + 8;

    const int ntiles = q0 / BN + 2;

    // ---- prologue: stage tile 0 into buf0 ----
    {
        float4 kreg[4], vreg[4];
        stage_ldg(Kg, Vg, 0, tid, kreg, vreg);
        stage_sts(dsm, tid, kreg, vreg);
    }
    __syncthreads();

    for (int t = 0; t < ntiles; t++) {
        const int kv0 = t * BN;
        char* bufR = dsm + (t & 1) * BUF_BYTES;
        char* bufW = dsm + ((t & 1) ^ 1) * BUF_BYTES;
        const bool have_next = (t + 1 < ntiles);

        // ---- early LDG for tile t+1 ----
        float4 kreg[4], vreg[4];
        if (have_next) stage_ldg(Kg, Vg, kv0 + BN, tid, kreg, vreg);

        // ---- GEMM1: S = Q @ K^T (3x bf16 m16n8k16) ----
        float sacc[8][4];
        #pragma unroll
        for (int j = 0; j < 8; j++)
            sacc[j][0] = sacc[j][1] = sacc[j][2] = sacc[j][3] = 0.f;
        #pragma unroll
        for (int kc = 0; kc < 4; kc++) {
            #pragma unroll
            for (int j = 0; j < 8; j++) {
                float4 fr = *(const float4*)(bufR + (j * 4 + kc) * KFP + lane * 16);
                uint32_t bh0 = __float_as_uint(fr.x), bh1 = __float_as_uint(fr.y);
                uint32_t bl0 = __float_as_uint(fr.z), bl1 = __float_as_uint(fr.w);
                mma16(sacc[j], qh[kc], bh0, bh1);
                mma16(sacc[j], ql[kc], bh0, bh1);
                mma16(sacc[j], qh[kc], bl0, bl1);
            }
        }

        // ---- causal mask + online softmax ----
        float mx0 = -INFINITY, mx1 = -INFINITY;
        #pragma unroll
        for (int j = 0; j < 8; j++) {
            const int c0 = kv0 + 8 * j + 2 * ctg, c1 = c0 + 1;
            if (c0 > r0g) sacc[j][0] = -INFINITY;
            if (c1 > r0g) sacc[j][1] = -INFINITY;
            if (c0 > r1g) sacc[j][2] = -INFINITY;
            if (c1 > r1g) sacc[j][3] = -INFINITY;
            mx0 = fmaxf(mx0, fmaxf(sacc[j][0], sacc[j][1]));
            mx1 = fmaxf(mx1, fmaxf(sacc[j][2], sacc[j][3]));
        }
        mx0 = fmaxf(mx0, __shfl_xor_sync(0xffffffffu, mx0, 1));
        mx0 = fmaxf(mx0, __shfl_xor_sync(0xffffffffu, mx0, 2));
        mx1 = fmaxf(mx1, __shfl_xor_sync(0xffffffffu, mx1, 1));
        mx1 = fmaxf(mx1, __shfl_xor_sync(0xffffffffu, mx1, 2));

        const float mn0 = fmaxf(m0, mx0), mn1 = fmaxf(m1, mx1);
        const float a0s = __expf(m0 - mn0), a1s = __expf(m1 - mn1);
        float s0 = 0.f, s1 = 0.f;
        #pragma unroll
        for (int j = 0; j < 8; j++) {
            float p0 = __expf(sacc[j][0] - mn0), p1 = __expf(sacc[j][1] - mn0);
            float p2 = __expf(sacc[j][2] - mn1), p3 = __expf(sacc[j][3] - mn1);
            sacc[j][0] = p0; sacc[j][1] = p1; sacc[j][2] = p2; sacc[j][3] = p3;
            s0 += p0 + p1; s1 += p2 + p3;
        }
        s0 += __shfl_xor_sync(0xffffffffu, s0, 1);
        s0 += __shfl_xor_sync(0xffffffffu, s0, 2);
        s1 += __shfl_xor_sync(0xffffffffu, s1, 1);
        s1 += __shfl_xor_sync(0xffffffffu, s1, 2);
        l0 = l0 * a0s + s0; m0 = mn0;
        l1 = l1 * a1s + s1; m1 = mn1;
        #pragma unroll
        for (int j = 0; j < 8; j++) {
            o[j][0] *= a0s; o[j][1] *= a0s; o[j][2] *= a1s; o[j][3] *= a1s;
        }

        // ---- C-fragment -> A-fragment (P) via quad shuffles ----
        uint32_t pa[8][4];
        const int bl  = lane & ~3;
        const int sA  = bl + (ctg >> 1);
        const int sB  = sA + 2;
        const bool oddc = (ctg & 1);
        #pragma unroll
        for (int j = 0; j < 8; j++) {
            float x0 = __shfl_sync(0xffffffffu, sacc[j][0], sA);
            float x1 = __shfl_sync(0xffffffffu, sacc[j][1], sA);
            float y0 = __shfl_sync(0xffffffffu, sacc[j][0], sB);
            float y1 = __shfl_sync(0xffffffffu, sacc[j][1], sB);
            float z0 = __shfl_sync(0xffffffffu, sacc[j][2], sA);
            float z1 = __shfl_sync(0xffffffffu, sacc[j][3], sA);
            float u0 = __shfl_sync(0xffffffffu, sacc[j][2], sB);
            float u1 = __shfl_sync(0xffffffffu, sacc[j][3], sB);
            pa[j][0] = tf32u(oddc ? x1 : x0);
            pa[j][1] = tf32u(oddc ? z1 : z0);
            pa[j][2] = tf32u(oddc ? y1 : y0);
            pa[j][3] = tf32u(oddc ? u1 : u0);
        }

        // ---- GEMM2: O += P @ V (tf32) ----
        #pragma unroll
        for (int kc = 0; kc < 8; kc++) {
            #pragma unroll
            for (int jd = 0; jd < 8; jd++) {
                float2 b = *(const float2*)(bufR + KF_BYTES + (kc * 8 + jd) * VFP + lane * 8);
                mma8(o[jd], pa[kc], __float_as_uint(b.x), __float_as_uint(b.y));
            }
        }

        // ---- store staged tile t+1 into the other buffer ----
        if (have_next) stage_sts(bufW, tid, kreg, vreg);
        __syncthreads();
    }

    // ---- epilogue ----
    const float i0 = 1.f / l0, i1 = 1.f / l1;
    float* out0 = Og + ((size_t)bh * SEQ + r0g) * DIM;
    float* out1 = Og + ((size_t)bh * SEQ + r1g) * DIM;
    #pragma unroll
    for (int jd = 0; jd < 8; jd++) {
        const int c = 8 * jd + 2 * ctg;
        *(float2*)(out0 + c) = make_float2(o[jd][0] * i0, o[jd][1] * i0);
        *(float2*)(out1 + c) = make_float2(o[jd][2] * i1, o[jd][3] * i1);
    }
}

// ---------------------------------------------------------------------------
extern "C" void kernel_launch(void* const* d_in, const int* in_sizes, int n_in,
                              void* d_out, int out_size) {
    const float* Q = (const float*)d_in[0];
    const float* K = (const float*)d_in[1];
    const float* V = (const float*)d_in[2];
    float* O = (float*)d_out;

    cudaFuncSetAttribute(flash_kernel, cudaFuncAttributeMaxDynamicSharedMemorySize, SM_TOTAL);

    const int total = BH * SEQ * (DIM / 2);
    rope_kernel<<<(total + 255) / 256, 256>>>(Q, K);

    dim3 grid(SEQ / BM, BH);
    flash_kernel<<<grid, 256, SM_TOTAL>>>(V, O);
}

// round 10
// speedup vs baseline: 3.7988x; 1.2918x over previous
#include <cuda_runtime.h>
#include <cuda_bf16.h>
#include <cuda_fp16.h>
#include <math.h>
#include <stdint.h>

#define BATCH 2
#define HEADS 16
#define SEQ   2048
#define DIM   64
#define BH    (BATCH*HEADS)
#define BM    128
#define BN    64

// K fragment blocks (j,kc): kc in 0..3 (k16 chunks), 32 lanes x 16B {hi0,hi1,lo0,lo1} bf16
// V fragment blocks (kc,jd): kc in 0..3 (k16 chunks), 32 lanes x 8B {b0,b1} f16x2
#define KFP 528                  // 512 + 16 pad
#define VFP2 264                 // 256 + 8 pad
#define KF_BYTES (8*4*KFP)       // 16896
#define BUF_BYTES (KF_BYTES + 4*8*VFP2)   // 16896 + 8448 = 25344
#define SM_TOTAL (2*BUF_BYTES)   // 50688

__device__ __align__(16) float g_Qr[BH*SEQ*DIM];
__device__ __align__(16) float g_Kr[BH*SEQ*DIM];

// split (f0,f1) into bf16 hi pair + bf16 residual pair, packed bf16x2 (low half = f0)
__device__ __forceinline__ void bsplit2(float f0, float f1, uint32_t& hi, uint32_t& lo) {
    __nv_bfloat16 h0 = __float2bfloat16_rn(f0);
    __nv_bfloat16 h1 = __float2bfloat16_rn(f1);
    float r0 = f0 - __bfloat162float(h0);
    float r1 = f1 - __bfloat162float(h1);
    __nv_bfloat162 H = {h0, h1};
    __nv_bfloat162 L = {__float2bfloat16_rn(r0), __float2bfloat16_rn(r1)};
    hi = *(uint32_t*)&H;
    lo = *(uint32_t*)&L;
}

// bf16 m16n8k16 (GEMM1)
__device__ __forceinline__ void mma16(float* c, const uint32_t* a, uint32_t b0, uint32_t b1) {
    asm volatile("mma.sync.aligned.m16n8k16.row.col.f32.bf16.bf16.f32 "
        "{%0,%1,%2,%3}, {%4,%5,%6,%7}, {%8,%9}, {%0,%1,%2,%3};"
        : "+f"(c[0]), "+f"(c[1]), "+f"(c[2]), "+f"(c[3])
        : "r"(a[0]), "r"(a[1]), "r"(a[2]), "r"(a[3]), "r"(b0), "r"(b1));
}
// f16 m16n8k16 (GEMM2)
__device__ __forceinline__ void mma16f(float* c, const uint32_t* a, uint32_t b0, uint32_t b1) {
    asm volatile("mma.sync.aligned.m16n8k16.row.col.f32.f16.f16.f32 "
        "{%0,%1,%2,%3}, {%4,%5,%6,%7}, {%8,%9}, {%0,%1,%2,%3};"
        : "+f"(c[0]), "+f"(c[1]), "+f"(c[2]), "+f"(c[3])
        : "r"(a[0]), "r"(a[1]), "r"(a[2]), "r"(a[3]), "r"(b0), "r"(b1));
}

// ---------------------------------------------------------------------------
__global__ void rope_kernel(const float* __restrict__ Q, const float* __restrict__ K) {
    int idx = blockIdx.x * blockDim.x + threadIdx.x;
    const int half = DIM / 2;
    if (idx >= BH * SEQ * half) return;
    int i   = idx & (half - 1);
    int row = idx >> 5;
    int s   = row & (SEQ - 1);
    float div = expf((float)(2 * i) * (-9.210340371976184f / 64.0f));
    float sv, cv; sincosf((float)s * div, &sv, &cv);
    int base = row * DIM + 2 * i;
    float qe = Q[base], qo = Q[base + 1];
    g_Qr[base]     = qe * cv - qo * sv;
    g_Qr[base + 1] = qe * sv + qo * cv;
    float ke = K[base], ko = K[base + 1];
    g_Kr[base]     = ke * cv - ko * sv;
    g_Kr[base + 1] = ke * sv + ko * cv;
}

// ---------------------------------------------------------------------------
__device__ __forceinline__ void stage_ldg(const float* __restrict__ Kg,
                                          const float* __restrict__ Vg,
                                          int kv0, int tid,
                                          float4* kreg, float4* v0, float4* v1) {
    #pragma unroll
    for (int it = 0; it < 4; it++) {
        int c = tid + 256 * it;
        int row = c >> 4, d4 = (c & 15) << 2;
        kreg[it] = *(const float4*)(Kg + (size_t)(kv0 + row) * DIM + d4);
    }
    #pragma unroll
    for (int s = 0; s < 2; s++) {
        int item = tid + 256 * s;             // 512 items: row-pairs x d4-chunks
        int rp = item >> 4, d4 = (item & 15) << 2;
        v0[s] = *(const float4*)(Vg + (size_t)(kv0 + 2 * rp) * DIM + d4);
        v1[s] = *(const float4*)(Vg + (size_t)(kv0 + 2 * rp + 1) * DIM + d4);
    }
}

__device__ __forceinline__ void stage_sts(char* buf, int tid, const float4* kreg,
                                          const float4* v0, const float4* v1) {
    #pragma unroll
    for (int it = 0; it < 4; it++) {
        int c = tid + 256 * it;
        int row = c >> 4, d4 = (c & 15) << 2;
        // K -> bf16 hi/lo fragment layout: block (j,kc), slot (g*4+c0), half at +4B
        int j = row >> 3, g = row & 7;
        int kc = d4 >> 4;
        int pp = (d4 >> 1) & 7;
        int c0 = pp & 3, halfb = (pp >> 2) * 4;
        uint32_t hi0, lo0, hi1, lo1;
        bsplit2(kreg[it].x, kreg[it].y, hi0, lo0);
        bsplit2(kreg[it].z, kreg[it].w, hi1, lo1);
        char* kb = buf + (j * 4 + kc) * KFP + (g * 4 + c0) * 16 + halfb;
        *(uint32_t*)(kb)      = hi0;
        *(uint32_t*)(kb + 8)  = lo0;
        *(uint32_t*)(kb + 16) = hi1;
        *(uint32_t*)(kb + 24) = lo1;
    }
    // V -> f16 B-fragment layout for m16n8k16: block (kc,jd), lane (gid*4+ctg), slot b0/b1
    #pragma unroll
    for (int s = 0; s < 2; s++) {
        int item = tid + 256 * s;
        int rp = item >> 4, d4 = (item & 15) << 2;   // keys 2rp,2rp+1 ; dims d4..d4+3
        int kc  = rp >> 3;
        int ctg = rp & 3;
        int slot = (rp & 4) ? 4 : 0;
        const float* a = (const float*)&v0[s];
        const float* b = (const float*)&v1[s];
        #pragma unroll
        for (int i = 0; i < 4; i++) {
            int n = d4 + i, jd = n >> 3, gid = n & 7;
            __half2 h = __floats2half2_rn(a[i], b[i]);   // low = V[2rp][n], high = V[2rp+1][n]
            *(uint32_t*)(buf + KF_BYTES + (kc * 8 + jd) * VFP2 + (gid * 4 + ctg) * 8 + slot)
                = *(uint32_t*)&h;
        }
    }
}

// ---------------------------------------------------------------------------
__global__ __launch_bounds__(256, 1) void flash_kernel(const float* __restrict__ Vall,
                                                       float* __restrict__ Og) {
    extern __shared__ __align__(16) char dsm[];

    const int tid  = threadIdx.x;
    const int w    = tid >> 5;
    const int lane = tid & 31;
    const int gid  = lane >> 2;
    const int ctg  = lane & 3;

    const int bh = blockIdx.y;
    const int q0 = ((int)(gridDim.x - 1) - (int)blockIdx.x) * BM;   // heavy tiles first
    const float* Qg = g_Qr + ((size_t)bh * SEQ + q0 + w * 16) * DIM;
    const float* Kg = g_Kr + (size_t)bh * SEQ * DIM;
    const float* Vg = Vall + (size_t)bh * SEQ * DIM;

    // ---- persistent Q A-fragments, bf16 hi/lo, m16n8k16 layout: 32 regs ----
    uint32_t qh[4][4], ql[4][4];
    #pragma unroll
    for (int kc = 0; kc < 4; kc++) {
        const int e0 = 16 * kc + 2 * ctg;
        bsplit2(Qg[gid * DIM + e0],           Qg[gid * DIM + e0 + 1],       qh[kc][0], ql[kc][0]);
        bsplit2(Qg[(gid + 8) * DIM + e0],     Qg[(gid + 8) * DIM + e0 + 1], qh[kc][1], ql[kc][1]);
        bsplit2(Qg[gid * DIM + e0 + 8],       Qg[gid * DIM + e0 + 9],       qh[kc][2], ql[kc][2]);
        bsplit2(Qg[(gid + 8) * DIM + e0 + 8], Qg[(gid + 8) * DIM + e0 + 9], qh[kc][3], ql[kc][3]);
    }

    float o[8][4];
    #pragma unroll
    for (int j = 0; j < 8; j++) { o[j][0] = o[j][1] = o[j][2] = o[j][3] = 0.f; }
    float m0 = -INFINITY, m1 = -INFINITY, l0 = 0.f, l1 = 0.f;
    const int r0g = q0 + w * 16 + gid;
    const int r1g = r0g + 8;

    const int ntiles = q0 / BN + 2;

    // ---- prologue: stage tile 0 into buf0 ----
    {
        float4 kreg[4], v0[2], v1[2];
        stage_ldg(Kg, Vg, 0, tid, kreg, v0, v1);
        stage_sts(dsm, tid, kreg, v0, v1);
    }
    __syncthreads();

    for (int t = 0; t < ntiles; t++) {
        const int kv0 = t * BN;
        char* bufR = dsm + (t & 1) * BUF_BYTES;
        char* bufW = dsm + ((t & 1) ^ 1) * BUF_BYTES;
        const bool have_next = (t + 1 < ntiles);

        // ---- early LDG for tile t+1 ----
        float4 kreg[4], v0[2], v1[2];
        if (have_next) stage_ldg(Kg, Vg, kv0 + BN, tid, kreg, v0, v1);

        // ---- GEMM1: S = Q @ K^T (3x bf16 m16n8k16) ----
        float sacc[8][4];
        #pragma unroll
        for (int j = 0; j < 8; j++)
            sacc[j][0] = sacc[j][1] = sacc[j][2] = sacc[j][3] = 0.f;
        #pragma unroll
        for (int kc = 0; kc < 4; kc++) {
            #pragma unroll
            for (int j = 0; j < 8; j++) {
                float4 fr = *(const float4*)(bufR + (j * 4 + kc) * KFP + lane * 16);
                uint32_t bh0 = __float_as_uint(fr.x), bh1 = __float_as_uint(fr.y);
                uint32_t bl0 = __float_as_uint(fr.z), bl1 = __float_as_uint(fr.w);
                mma16(sacc[j], qh[kc], bh0, bh1);
                mma16(sacc[j], ql[kc], bh0, bh1);
                mma16(sacc[j], qh[kc], bl0, bl1);
            }
        }

        // ---- causal mask (warp-uniform skip) + online softmax ----
        if (kv0 + BN - 1 > q0 + w * 16) {
            #pragma unroll
            for (int j = 0; j < 8; j++) {
                const int c0 = kv0 + 8 * j + 2 * ctg, c1 = c0 + 1;
                if (c0 > r0g) sacc[j][0] = -INFINITY;
                if (c1 > r0g) sacc[j][1] = -INFINITY;
                if (c0 > r1g) sacc[j][2] = -INFINITY;
                if (c1 > r1g) sacc[j][3] = -INFINITY;
            }
        }
        float mx0 = -INFINITY, mx1 = -INFINITY;
        #pragma unroll
        for (int j = 0; j < 8; j++) {
            mx0 = fmaxf(mx0, fmaxf(sacc[j][0], sacc[j][1]));
            mx1 = fmaxf(mx1, fmaxf(sacc[j][2], sacc[j][3]));
        }
        mx0 = fmaxf(mx0, __shfl_xor_sync(0xffffffffu, mx0, 1));
        mx0 = fmaxf(mx0, __shfl_xor_sync(0xffffffffu, mx0, 2));
        mx1 = fmaxf(mx1, __shfl_xor_sync(0xffffffffu, mx1, 1));
        mx1 = fmaxf(mx1, __shfl_xor_sync(0xffffffffu, mx1, 2));

        const float mn0 = fmaxf(m0, mx0), mn1 = fmaxf(m1, mx1);
        const float a0s = __expf(m0 - mn0), a1s = __expf(m1 - mn1);
        float s0 = 0.f, s1 = 0.f;
        #pragma unroll
        for (int j = 0; j < 8; j++) {
            float p0 = __expf(sacc[j][0] - mn0), p1 = __expf(sacc[j][1] - mn0);
            float p2 = __expf(sacc[j][2] - mn1), p3 = __expf(sacc[j][3] - mn1);
            sacc[j][0] = p0; sacc[j][1] = p1; sacc[j][2] = p2; sacc[j][3] = p3;
            s0 += p0 + p1; s1 += p2 + p3;
        }
        s0 += __shfl_xor_sync(0xffffffffu, s0, 1);
        s0 += __shfl_xor_sync(0xffffffffu, s0, 2);
        s1 += __shfl_xor_sync(0xffffffffu, s1, 1);
        s1 += __shfl_xor_sync(0xffffffffu, s1, 2);
        l0 = l0 * a0s + s0; m0 = mn0;
        l1 = l1 * a1s + s1; m1 = mn1;
        #pragma unroll
        for (int j = 0; j < 8; j++) {
            o[j][0] *= a0s; o[j][1] *= a0s; o[j][2] *= a1s; o[j][3] *= a1s;
        }

        // ---- GEMM2: O += P @ V (f16 m16n8k16; C->A pack is shuffle-free) ----
        #pragma unroll
        for (int kc = 0; kc < 4; kc++) {
            __half2 a0 = __floats2half2_rn(sacc[2*kc][0],   sacc[2*kc][1]);
            __half2 a1 = __floats2half2_rn(sacc[2*kc][2],   sacc[2*kc][3]);
            __half2 a2 = __floats2half2_rn(sacc[2*kc+1][0], sacc[2*kc+1][1]);
            __half2 a3 = __floats2half2_rn(sacc[2*kc+1][2], sacc[2*kc+1][3]);
            uint32_t pa[4] = {*(uint32_t*)&a0, *(uint32_t*)&a1,
                              *(uint32_t*)&a2, *(uint32_t*)&a3};
            #pragma unroll
            for (int jd = 0; jd < 8; jd++) {
                uint2 b = *(const uint2*)(bufR + KF_BYTES + (kc * 8 + jd) * VFP2 + lane * 8);
                mma16f(o[jd], pa, b.x, b.y);
            }
        }

        // ---- store staged tile t+1 into the other buffer ----
        if (have_next) stage_sts(bufW, tid, kreg, v0, v1);
        __syncthreads();
    }

    // ---- epilogue ----
    const float i0 = 1.f / l0, i1 = 1.f / l1;
    float* out0 = Og + ((size_t)bh * SEQ + r0g) * DIM;
    float* out1 = Og + ((size_t)bh * SEQ + r1g) * DIM;
    #pragma unroll
    for (int jd = 0; jd < 8; jd++) {
        const int c = 8 * jd + 2 * ctg;
        *(float2*)(out0 + c) = make_float2(o[jd][0] * i0, o[jd][1] * i0);
        *(float2*)(out1 + c) = make_float2(o[jd][2] * i1, o[jd][3] * i1);
    }
}

// ---------------------------------------------------------------------------
extern "C" void kernel_launch(void* const* d_in, const int* in_sizes, int n_in,
                              void* d_out, int out_size) {
    const float* Q = (const float*)d_in[0];
    const float* K = (const float*)d_in[1];
    const float* V = (const float*)d_in[2];
    float* O = (float*)d_out;

    cudaFuncSetAttribute(flash_kernel, cudaFuncAttributeMaxDynamicSharedMemorySize, SM_TOTAL);

    const int total = BH * SEQ * (DIM / 2);
    rope_kernel<<<(total + 255) / 256, 256>>>(Q, K);

    dim3 grid(SEQ / BM, BH);
    flash_kernel<<<grid, 256, SM_TOTAL>>>(V, O);
}

// round 12
// speedup vs baseline: 4.0175x; 1.0576x over previous
#include <cuda_runtime.h>
#include <cuda_bf16.h>
#include <cuda_fp16.h>
#include <math.h>
#include <stdint.h>

#define BATCH 2
#define HEADS 16
#define SEQ   2048
#define DIM   64
#define BH    (BATCH*HEADS)
#define BM    128
#define BN    64
#define NT    (SEQ/BN)          // 32 kv tiles per bh

// per-tile fragment-ordered global layouts
#define KT_U32 4096             // K tile: 32 blocks x 32 lanes x 16B = 16384 B
#define VT_U32 2048             // V tile: 32 blocks x 32 lanes x 8B  =  8192 B
#define KT_BYTES 16384
#define VT_BYTES 8192
#define STAGE_BYTES (KT_BYTES + VT_BYTES)   // 24576
#define SM_TOTAL (3 * STAGE_BYTES)          // 73728 (3-stage ring)

__device__ __align__(16) float    g_Qr[BH*SEQ*DIM];
__device__ __align__(16) uint32_t g_Kf[BH*NT*KT_U32];
__device__ __align__(16) uint32_t g_Vf[BH*NT*VT_U32];

// ---------------------------------------------------------------------------
__device__ __forceinline__ void bsplit2(float f0, float f1, uint32_t& hi, uint32_t& lo) {
    __nv_bfloat16 h0 = __float2bfloat16_rn(f0);
    __nv_bfloat16 h1 = __float2bfloat16_rn(f1);
    float r0 = f0 - __bfloat162float(h0);
    float r1 = f1 - __bfloat162float(h1);
    __nv_bfloat162 H = {h0, h1};
    __nv_bfloat162 L = {__float2bfloat16_rn(r0), __float2bfloat16_rn(r1)};
    hi = *(uint32_t*)&H;
    lo = *(uint32_t*)&L;
}
__device__ __forceinline__ float ex2f(float x) {
    float r; asm("ex2.approx.f32 %0, %1;" : "=f"(r) : "f"(x)); return r;
}
__device__ __forceinline__ void mma16(float* c, const uint32_t* a, uint32_t b0, uint32_t b1) {
    asm volatile("mma.sync.aligned.m16n8k16.row.col.f32.bf16.bf16.f32 "
        "{%0,%1,%2,%3}, {%4,%5,%6,%7}, {%8,%9}, {%0,%1,%2,%3};"
        : "+f"(c[0]), "+f"(c[1]), "+f"(c[2]), "+f"(c[3])
        : "r"(a[0]), "r"(a[1]), "r"(a[2]), "r"(a[3]), "r"(b0), "r"(b1));
}
__device__ __forceinline__ void mma16f(float* c, const uint32_t* a, uint32_t b0, uint32_t b1) {
    asm volatile("mma.sync.aligned.m16n8k16.row.col.f32.f16.f16.f32 "
        "{%0,%1,%2,%3}, {%4,%5,%6,%7}, {%8,%9}, {%0,%1,%2,%3};"
        : "+f"(c[0]), "+f"(c[1]), "+f"(c[2]), "+f"(c[3])
        : "r"(a[0]), "r"(a[1]), "r"(a[2]), "r"(a[3]), "r"(b0), "r"(b1));
}
__device__ __forceinline__ uint32_t smem_u32(const void* p) {
    uint32_t a;
    asm("{ .reg .u64 t; cvta.to.shared.u64 t, %1; cvt.u32.u64 %0, t; }" : "=r"(a) : "l"(p));
    return a;
}
__device__ __forceinline__ void cp16(uint32_t saddr, const void* g) {
    asm volatile("cp.async.cg.shared.global [%0], [%1], 16;" :: "r"(saddr), "l"(g));
}
#define CP_COMMIT() asm volatile("cp.async.commit_group;" ::: "memory")
#define CP_WAIT(n)  asm volatile("cp.async.wait_group %0;" :: "n"(n) : "memory")

// ---------------------------------------------------------------------------
// RoPE prep: Q -> fp32 g_Qr ; K -> (RoPE * log2e) bf16 hi/lo, fragment-ordered g_Kf
// ---------------------------------------------------------------------------
__global__ void rope_kernel(const float* __restrict__ Q, const float* __restrict__ K) {
    int idx = blockIdx.x * blockDim.x + threadIdx.x;
    if (idx >= BH * SEQ * 32) return;
    int i   = idx & 31;           // pair index 0..31
    int row = idx >> 5;
    int s   = row & (SEQ - 1);
    int bh  = row >> 11;
    float div = expf((float)(2 * i) * (-9.210340371976184f / 64.0f));
    float sv, cv; sincosf((float)s * div, &sv, &cv);
    int base = row * DIM + 2 * i;
    float qe = Q[base], qo = Q[base + 1];
    g_Qr[base]     = qe * cv - qo * sv;
    g_Qr[base + 1] = qe * sv + qo * cv;

    const float L2E = 1.4426950408889634f;       // scores computed in log2 domain
    float ke = K[base], ko = K[base + 1];
    float k0 = (ke * cv - ko * sv) * L2E;
    float k1 = (ke * sv + ko * cv) * L2E;
    uint32_t hi, lo; bsplit2(k0, k1, hi, lo);
    int tile = s >> 6;
    int j = (s >> 3) & 7, g = s & 7;
    int kc = i >> 3, pp = i & 7, c0 = pp & 3, hq = pp >> 2;
    uint32_t* kb = g_Kf + (size_t)(bh * NT + tile) * KT_U32
                 + (j * 4 + kc) * 128 + (g * 4 + c0) * 4 + hq;
    kb[0] = hi;     // hi bf16x2
    kb[2] = lo;     // lo bf16x2 (+8 bytes)
}

// V -> f16x2 pairs, fragment-ordered g_Vf
__global__ void vprep_kernel(const float* __restrict__ V) {
    int idx = blockIdx.x * blockDim.x + threadIdx.x;
    if (idx >= BH * NT * 32 * 64) return;
    int n    = idx & 63;
    int rp   = (idx >> 6) & 31;
    int tile = (idx >> 11) & 31;
    int bh   = idx >> 16;
    const float* vb = V + ((size_t)bh * SEQ + tile * 64) * DIM;
    __half2 h = __floats2half2_rn(vb[(2 * rp) * DIM + n], vb[(2 * rp + 1) * DIM + n]);
    int kc = rp >> 3, ctg = rp & 3, slot = (rp & 4) ? 1 : 0;
    int jd = n >> 3, gid = n & 7;
    g_Vf[(size_t)(bh * NT + tile) * VT_U32
         + (kc * 8 + jd) * 64 + (gid * 4 + ctg) * 2 + slot] = *(uint32_t*)&h;
}

// ---------------------------------------------------------------------------
__global__ __launch_bounds__(256, 1) void flash_kernel(float* __restrict__ Og) {
    extern __shared__ __align__(16) char dsm[];
    const uint32_t sbase = smem_u32(dsm);

    const int tid  = threadIdx.x;
    const int w    = tid >> 5;
    const int lane = tid & 31;
    const int gid  = lane >> 2;
    const int ctg  = lane & 3;

    const int bh = blockIdx.y;
    const int q0 = ((int)(gridDim.x - 1) - (int)blockIdx.x) * BM;   // heavy tiles first
    const float* Qg = g_Qr + ((size_t)bh * SEQ + q0 + w * 16) * DIM;
    const uint32_t* Kt = g_Kf + (size_t)bh * NT * KT_U32;
    const uint32_t* Vt = g_Vf + (size_t)bh * NT * VT_U32;

    // ---- persistent Q A-fragments, bf16 hi/lo: 32 regs ----
    uint32_t qh[4][4], ql[4][4];
    #pragma unroll
    for (int kc = 0; kc < 4; kc++) {
        const int e0 = 16 * kc + 2 * ctg;
        bsplit2(Qg[gid * DIM + e0],           Qg[gid * DIM + e0 + 1],       qh[kc][0], ql[kc][0]);
        bsplit2(Qg[(gid + 8) * DIM + e0],     Qg[(gid + 8) * DIM + e0 + 1], qh[kc][1], ql[kc][1]);
        bsplit2(Qg[gid * DIM + e0 + 8],       Qg[gid * DIM + e0 + 9],       qh[kc][2], ql[kc][2]);
        bsplit2(Qg[(gid + 8) * DIM + e0 + 8], Qg[(gid + 8) * DIM + e0 + 9], qh[kc][3], ql[kc][3]);
    }

    float o[8][4];
    #pragma unroll
    for (int j = 0; j < 8; j++) { o[j][0] = o[j][1] = o[j][2] = o[j][3] = 0.f; }
    float m0 = -INFINITY, m1 = -INFINITY, l0 = 0.f, l1 = 0.f;
    const int r0g = q0 + w * 16 + gid;
    const int r1g = r0g + 8;

    const int ntiles = q0 / BN + 2;

    // async copy of tile t into ring stage t%3 (contiguous, fragment-ordered)
    auto issue = [&](int t) {
        uint32_t dst = sbase + (uint32_t)(t % 3) * STAGE_BYTES;
        const char* gk = (const char*)(Kt + (size_t)t * KT_U32);
        const char* gv = (const char*)(Vt + (size_t)t * VT_U32);
        #pragma unroll
        for (int it = 0; it < 4; it++)
            cp16(dst + (tid + it * 256) * 16, gk + (tid + it * 256) * 16);
        #pragma unroll
        for (int it = 0; it < 2; it++)
            cp16(dst + KT_BYTES + (tid + it * 256) * 16, gv + (tid + it * 256) * 16);
    };

    issue(0); CP_COMMIT();
    if (1 < ntiles) { issue(1); CP_COMMIT(); }

    for (int t = 0; t < ntiles; t++) {
        const int kv0 = t * BN;
        if (t + 1 < ntiles) { CP_WAIT(1); } else { CP_WAIT(0); }
        __syncthreads();                    // stage t visible to all warps
        if (t + 2 < ntiles) { issue(t + 2); CP_COMMIT(); }   // safe: all warps past t-1

        const char* bufR = dsm + (t % 3) * STAGE_BYTES;

        // ---- GEMM1: S_log2 = Q @ (K*log2e)^T  (3x bf16 m16n8k16) ----
        float sacc[8][4];
        #pragma unroll
        for (int j = 0; j < 8; j++)
            sacc[j][0] = sacc[j][1] = sacc[j][2] = sacc[j][3] = 0.f;
        #pragma unroll
        for (int kc = 0; kc < 4; kc++) {
            #pragma unroll
            for (int j = 0; j < 8; j++) {
                float4 fr = *(const float4*)(bufR + (j * 4 + kc) * 512 + lane * 16);
                uint32_t bh0 = __float_as_uint(fr.x), bh1 = __float_as_uint(fr.y);
                uint32_t bl0 = __float_as_uint(fr.z), bl1 = __float_as_uint(fr.w);
                mma16(sacc[j], qh[kc], bh0, bh1);
                mma16(sacc[j], ql[kc], bh0, bh1);
                mma16(sacc[j], qh[kc], bl0, bl1);
            }
        }

        // ---- causal mask (warp-uniform skip) + online softmax (log2 domain) ----
        if (kv0 + BN - 1 > q0 + w * 16) {
            #pragma unroll
            for (int j = 0; j < 8; j++) {
                const int c0 = kv0 + 8 * j + 2 * ctg, c1 = c0 + 1;
                if (c0 > r0g) sacc[j][0] = -INFINITY;
                if (c1 > r0g) sacc[j][1] = -INFINITY;
                if (c0 > r1g) sacc[j][2] = -INFINITY;
                if (c1 > r1g) sacc[j][3] = -INFINITY;
            }
        }
        float mx0 = -INFINITY, mx1 = -INFINITY;
        #pragma unroll
        for (int j = 0; j < 8; j++) {
            mx0 = fmaxf(mx0, fmaxf(sacc[j][0], sacc[j][1]));
            mx1 = fmaxf(mx1, fmaxf(sacc[j][2], sacc[j][3]));
        }
        mx0 = fmaxf(mx0, __shfl_xor_sync(0xffffffffu, mx0, 1));
        mx0 = fmaxf(mx0, __shfl_xor_sync(0xffffffffu, mx0, 2));
        mx1 = fmaxf(mx1, __shfl_xor_sync(0xffffffffu, mx1, 1));
        mx1 = fmaxf(mx1, __shfl_xor_sync(0xffffffffu, mx1, 2));

        const float mn0 = fmaxf(m0, mx0), mn1 = fmaxf(m1, mx1);
        const float a0s = ex2f(m0 - mn0), a1s = ex2f(m1 - mn1);
        float s0 = 0.f, s1 = 0.f;
        #pragma unroll
        for (int j = 0; j < 8; j++) {
            float p0 = ex2f(sacc[j][0] - mn0), p1 = ex2f(sacc[j][1] - mn0);
            float p2 = ex2f(sacc[j][2] - mn1), p3 = ex2f(sacc[j][3] - mn1);
            sacc[j][0] = p0; sacc[j][1] = p1; sacc[j][2] = p2; sacc[j][3] = p3;
            s0 += p0 + p1; s1 += p2 + p3;
        }
        s0 += __shfl_xor_sync(0xffffffffu, s0, 1);
        s0 += __shfl_xor_sync(0xffffffffu, s0, 2);
        s1 += __shfl_xor_sync(0xffffffffu, s1, 1);
        s1 += __shfl_xor_sync(0xffffffffu, s1, 2);
        l0 = l0 * a0s + s0; m0 = mn0;
        l1 = l1 * a1s + s1; m1 = mn1;
        #pragma unroll
        for (int j = 0; j < 8; j++) {
            o[j][0] *= a0s; o[j][1] *= a0s; o[j][2] *= a1s; o[j][3] *= a1s;
        }

        // ---- GEMM2: O += P @ V (f16 m16n8k16; shuffle-free C->A pack) ----
        #pragma unroll
        for (int kc = 0; kc < 4; kc++) {
            __half2 a0 = __floats2half2_rn(sacc[2*kc][0],   sacc[2*kc][1]);
            __half2 a1 = __floats2half2_rn(sacc[2*kc][2],   sacc[2*kc][3]);
            __half2 a2 = __floats2half2_rn(sacc[2*kc+1][0], sacc[2*kc+1][1]);
            __half2 a3 = __floats2half2_rn(sacc[2*kc+1][2], sacc[2*kc+1][3]);
            uint32_t pa[4] = {*(uint32_t*)&a0, *(uint32_t*)&a1,
                              *(uint32_t*)&a2, *(uint32_t*)&a3};
            #pragma unroll
            for (int jd = 0; jd < 8; jd++) {
                uint2 b = *(const uint2*)(bufR + KT_BYTES + (kc * 8 + jd) * 256 + lane * 8);
                mma16f(o[jd], pa, b.x, b.y);
            }
        }
        // no trailing barrier: stage t%3 is only rewritten by issue(t+3), which
        // executes after the top-of-(t+1) __syncthreads
    }

    // ---- epilogue ----
    const float i0 = 1.f / l0, i1 = 1.f / l1;
    float* out0 = Og + ((size_t)bh * SEQ + r0g) * DIM;
    float* out1 = Og + ((size_t)bh * SEQ + r1g) * DIM;
    #pragma unroll
    for (int jd = 0; jd < 8; jd++) {
        const int c = 8 * jd + 2 * ctg;
        *(float2*)(out0 + c) = make_float2(o[jd][0] * i0, o[jd][1] * i0);
        *(float2*)(out1 + c) = make_float2(o[jd][2] * i1, o[jd][3] * i1);
    }
}

// ---------------------------------------------------------------------------
extern "C" void kernel_launch(void* const* d_in, const int* in_sizes, int n_in,
                              void* d_out, int out_size) {
    const float* Q = (const float*)d_in[0];
    const float* K = (const float*)d_in[1];
    const float* V = (const float*)d_in[2];
    float* O = (float*)d_out;

    cudaFuncSetAttribute(flash_kernel, cudaFuncAttributeMaxDynamicSharedMemorySize, SM_TOTAL);

    rope_kernel<<<(BH * SEQ * 32 + 255) / 256, 256>>>(Q, K);
    vprep_kernel<<<(BH * NT * 32 * 64 + 255) / 256, 256>>>(V);

    dim3 grid(SEQ / BM, BH);
    flash_kernel<<<grid, 256, SM_TOTAL>>>(O);
}